// round 5
// baseline (speedup 1.0000x reference)
#include <cuda_runtime.h>

#define NN   3072
#define EE   3072
#define ELG  6144
#define FF   64
#define HH   4
#define RPH  768        // input rows per head after .view scramble
#define TABH 9437184    // 3072*3072, lg keys offset by this

// -------- scratch (__device__ globals; no allocations allowed) --------
__device__ float g_NV[NN * 256];
__device__ float g_EV[EE * 256];
__device__ float g_srkp[2 * 48 * 4 * 64];   // partial srk sums [g][chunk][h][f]
__device__ float g_WT[2 * 256 * 64];        // transposed Wq (node, edge)
__device__ float g_att[2 * 4 * 3072];       // g=0: node att, g=1: edge att
__device__ unsigned char g_winN[EE];
__device__ unsigned char g_winL[ELG];
__device__ int g_tab[2 * TABH];             // dedup tournament table (zero invariant)

// packed f32x2 helpers (FFMA2 path — ptxas never emits this from plain C++)
__device__ __forceinline__ unsigned long long pk2(float w) {
    unsigned long long r;
    asm("mov.b64 %0, {%1, %1};" : "=l"(r) : "f"(w));
    return r;
}
__device__ __forceinline__ void ffma2(unsigned long long& d,
                                      unsigned long long a, unsigned long long b) {
    asm("fma.rn.f32x2 %0, %1, %2, %0;" : "+l"(d) : "l"(a), "l"(b));
}
__device__ __forceinline__ void unpk2(unsigned long long v, float& lo, float& hi) {
    asm("mov.b64 {%0, %1}, %2;" : "=f"(lo), "=f"(hi) : "l"(v));
}

// ======================= kernel A: all input-only work =======================
// roles by blockIdx.x:
//   [0,96)      srk partials (fused K projection, never materialized)
//   [96,480)    V gemms: NV (192 blocks), EV (192 blocks)
//   [480,516)   dedup atomicMax tournament (9216 edges)
//   [516,900)   zero output
//   [900,908)   transpose Wq (node 4 tiles, edge 4 tiles)
__global__ void __launch_bounds__(256) kA(
    const float* nin, const float* ein,
    const float* nkW, const float* nkb, const float* ekW, const float* ekb,
    const float* nvW, const float* nvb, const float* evW, const float* evb,
    const float* nqW, const float* eqW,
    const int* src, const int* dst, const int* lgs, const int* lgd,
    float* out)
{
    __shared__ __align__(16) float sm[8512];   // unioned per role (~34KB)
    int b = blockIdx.x, tid = threadIdx.x;

    if (b < 96) {
        // ---- srk role: chunk of 64 nodes (16 KM rows per head) ----
        int g = b / 48, chunk = b % 48;
        const float* in = g ? ein : nin;
        const float* W  = g ? ekW : nkW;
        const float* bk = g ? ekb : nkb;
        float* s_in4 = sm;           // 4 heads * 16 rows * stride 68 = 4352
        float* s_wT  = sm + 4352;    // 4 * 68
        float* s_km  = sm + 4624;    // 4 * 64

        #pragma unroll
        for (int h2 = 0; h2 < 4; h2++) {
            #pragma unroll
            for (int i = 0; i < 4; i++) {
                int idx = i * 256 + tid;
                int rr = idx >> 6, kk = idx & 63;
                s_in4[h2 * 1088 + rr * 68 + kk] =
                    in[(h2 * RPH + chunk * 16 + rr) * 64 + kk];
            }
        }
        {   // transpose tiny K weights: s_wT[c][k] = W[k*4+c]
            int k = tid >> 2, c = tid & 3;
            s_wT[c * 68 + k] = W[tid];
        }
        __syncthreads();
        // phase 1: k[h, n] = KM[h*768 + n/4, n%4]
        int h = tid >> 6, idx = tid & 63;
        int rl = idx >> 2, c = idx & 3;
        float acc = bk[c];
        const float4* arow = (const float4*)&s_in4[h * 1088 + rl * 68];
        const float4* wrow = (const float4*)&s_wT[c * 68];
        #pragma unroll
        for (int k4 = 0; k4 < 16; k4++) {
            float4 a = arow[k4], w = wrow[k4];
            acc += a.x * w.x + a.y * w.y + a.z * w.z + a.w * w.w;
        }
        s_km[h * 64 + rl * 4 + c] = acc;   // index == h*64 + local n
        __syncthreads();
        // phase 2: srk partial: srk[h,f] += in[n,f] * k[h,n] over 64 n
        int f = tid & 63;
        float sacc = 0.f;
        int n0 = chunk * 64;
        #pragma unroll 8
        for (int nl = 0; nl < 64; nl++)
            sacc += in[(n0 + nl) * 64 + f] * s_km[h * 64 + nl];
        g_srkp[((g * 48 + chunk) * 4 + h) * 64 + f] = sacc;

    } else if (b < 480) {
        // ---- V gemm role: [3072x64] @ [64x256] + bias, f32x2-packed ----
        int i2 = b - 96;
        int mat = i2 / 192;
        int rem = i2 % 192;
        int r0 = (rem >> 2) * 64, c0 = (rem & 3) * 64;
        const float* in = mat ? ein : nin;
        const float* W  = mat ? evW : nvW;
        const float* bb = mat ? evb : nvb;
        float* outv     = mat ? g_EV : g_NV;
        float* As = sm;                  // 64 k * stride 68 = 4352
        float* Ws = sm + 4352;           // 64*64
        float* Bs = sm + 8448;           // 64

        #pragma unroll
        for (int i = 0; i < 16; i++) {
            int idx = i * 256 + tid;
            int r = idx >> 6, k = idx & 63;
            As[k * 68 + r] = in[r0 * 64 + idx];
        }
        #pragma unroll
        for (int i = 0; i < 16; i++) {
            int idx = i * 256 + tid;
            int k = idx >> 6, cc = idx & 63;
            Ws[k * 64 + cc] = W[k * 256 + c0 + cc];
        }
        if (tid < 64) Bs[tid] = bb[c0 + tid];
        __syncthreads();

        int tx = tid & 15, ty = tid >> 4;
        int rl = ty * 4, cl = tx * 4;
        unsigned long long acc2[2][4];   // row-pairs (rl+2p, rl+2p+1) x 4 cols
        #pragma unroll
        for (int j = 0; j < 4; j++) {
            unsigned long long p = pk2(Bs[cl + j]);
            acc2[0][j] = p; acc2[1][j] = p;
        }

        #pragma unroll 16
        for (int k = 0; k < 64; k++) {
            ulonglong2 a = *(const ulonglong2*)&As[k * 68 + rl];
            float4 w = *(const float4*)&Ws[k * 64 + cl];
            unsigned long long wx = pk2(w.x), wy = pk2(w.y),
                               wz = pk2(w.z), ww = pk2(w.w);
            ffma2(acc2[0][0], a.x, wx); ffma2(acc2[1][0], a.y, wx);
            ffma2(acc2[0][1], a.x, wy); ffma2(acc2[1][1], a.y, wy);
            ffma2(acc2[0][2], a.x, wz); ffma2(acc2[1][2], a.y, wz);
            ffma2(acc2[0][3], a.x, ww); ffma2(acc2[1][3], a.y, ww);
        }
        #pragma unroll
        for (int p = 0; p < 2; p++) {
            float lo[4], hi[4];
            #pragma unroll
            for (int j = 0; j < 4; j++) unpk2(acc2[p][j], lo[j], hi[j]);
            *(float4*)&outv[(r0 + rl + 2 * p)     * 256 + c0 + cl] =
                make_float4(lo[0], lo[1], lo[2], lo[3]);
            *(float4*)&outv[(r0 + rl + 2 * p + 1) * 256 + c0 + cl] =
                make_float4(hi[0], hi[1], hi[2], hi[3]);
        }

    } else if (b < 516) {
        // ---- dedup tournament: atomicMax(tab[key], e+1) ----
        int e = (b - 480) * 256 + tid;
        if (e < EE) {
            atomicMax(&g_tab[src[e] * 3072 + dst[e]], e + 1);
        } else {
            int l = e - EE;
            atomicMax(&g_tab[TABH + lgs[l] * 3072 + lgd[l]], l + 1);
        }

    } else if (b < 900) {
        // ---- zero output ----
        int idx = (b - 516) * 256 + tid;
        ((float4*)out)[idx] = make_float4(0.f, 0.f, 0.f, 0.f);

    } else {
        // ---- transpose Wq: [64k][256c] -> WT[256c][64k] ----
        int t = b - 900;
        int mat = t >> 2, tile = t & 3;
        const float* W = mat ? eqW : nqW;
        float* s = sm;   // 64*65
        #pragma unroll
        for (int i = 0; i < 16; i++) {
            int idx = i * 256 + tid;
            int k = idx >> 6, c = idx & 63;
            s[k * 65 + c] = W[k * 256 + tile * 64 + c];
        }
        __syncthreads();
        #pragma unroll
        for (int i = 0; i < 16; i++) {
            int idx = i * 256 + tid;
            int c = idx >> 6, k = idx & 63;
            g_WT[mat * 16384 + (tile * 64 + c) * 64 + k] = s[k * 65 + c];
        }
    }
}

// ===== kernel BC: fused srk-reduce + c/d + logits + softmax (blocks 0-7) =====
// ===== blocks 8-16: read dedup winners from tournament table            =====
__global__ void __launch_bounds__(1024) kBC(
    const float* nin, const float* ein, const float* nqb, const float* eqb,
    const int* src, const int* dst, const int* lgs, const int* lgd)
{
    int tid = threadIdx.x;
    if (blockIdx.x >= 8) {
        int idx = (blockIdx.x - 8) * 1024 + tid;
        if (idx < EE) {
            g_winN[idx] = (g_tab[src[idx] * 3072 + dst[idx]] == idx + 1);
        } else if (idx < EE + ELG) {
            int l = idx - EE;
            g_winL[l] = (g_tab[TABH + lgs[l] * 3072 + lgd[l]] == l + 1);
        }
        return;
    }

    __shared__ float s_part[1024];
    __shared__ float s_srk[64];
    __shared__ __align__(16) float s_c[4 * 68];
    __shared__ float s_d[4];
    __shared__ float s_x[3072];
    __shared__ float s_red[32];
    __shared__ float s_v;

    int g = blockIdx.x >> 2, h = blockIdx.x & 3;
    const float* in = g ? ein : nin;

    // ---- phase 1: reduce srk partials (48 chunks) ----
    {
        int f = tid & 63, p = tid >> 6;    // 16 groups x 3 chunks
        float a = 0.f;
        #pragma unroll
        for (int q = 0; q < 3; q++)
            a += g_srkp[((g * 48 + p * 3 + q) * 4 + h) * 64 + f];
        s_part[tid] = a;
    }
    __syncthreads();
    if (tid < 64) {
        float a = 0.f;
        #pragma unroll
        for (int p = 0; p < 16; p++) a += s_part[p * 64 + tid];
        s_srk[tid] = a;
    }
    __syncthreads();

    // ---- phase 2: c[j][k] = sum_f Wq[k,64j+f]*srk[f];  d[j] = bq[j]::srk ----
    if (tid < 256) {
        int j = tid & 3, k = tid >> 2;
        const float* wt = g_WT + g * 16384 + j * 4096;   // WT[(j*64+f)*64 + k]
        float a = 0.f;
        #pragma unroll
        for (int f = 0; f < 64; f++)
            a += wt[f * 64 + k] * s_srk[f];
        s_c[j * 68 + k] = a;
    } else if (tid < 260) {
        int j = tid - 256;
        const float* bq = g ? eqb : nqb;
        float dd = 0.f;
        #pragma unroll
        for (int f = 0; f < 64; f++) dd += bq[j * 64 + f] * s_srk[f];
        s_d[j] = dd;
    }
    __syncthreads();

    // ---- phase 3: logits for all 3072 positions ----
    float lmax = -1e30f;
    #pragma unroll
    for (int i = 0; i < 3; i++) {
        int n = tid + i * 1024;
        int m = n >> 2, j = n & 3;
        const float4* row = (const float4*)(in + ((size_t)(h * RPH + m)) * 64);
        const float4* cj  = (const float4*)(s_c + j * 68);
        float a0 = 0.f, a1 = 0.f, a2 = 0.f, a3 = 0.f;
        #pragma unroll
        for (int k = 0; k < 16; k += 4) {
            float4 r0 = row[k + 0], c0 = cj[k + 0];
            float4 r1 = row[k + 1], c1 = cj[k + 1];
            float4 r2 = row[k + 2], c2 = cj[k + 2];
            float4 r3 = row[k + 3], c3 = cj[k + 3];
            a0 += r0.x * c0.x + r0.y * c0.y + r0.z * c0.z + r0.w * c0.w;
            a1 += r1.x * c1.x + r1.y * c1.y + r1.z * c1.z + r1.w * c1.w;
            a2 += r2.x * c2.x + r2.y * c2.y + r2.z * c2.z + r2.w * c2.w;
            a3 += r3.x * c3.x + r3.y * c3.y + r3.z * c3.z + r3.w * c3.w;
        }
        float x = (s_d[j] + ((a0 + a1) + (a2 + a3))) * 0.125f;
        s_x[n] = x;
        lmax = fmaxf(lmax, x);
    }

    // ---- phase 4: softmax over 3072 ----
    #pragma unroll
    for (int o = 16; o > 0; o >>= 1)
        lmax = fmaxf(lmax, __shfl_xor_sync(0xffffffffu, lmax, o));
    if ((tid & 31) == 0) s_red[tid >> 5] = lmax;
    __syncthreads();
    if (tid == 0) {
        float m2 = s_red[0];
        #pragma unroll
        for (int i = 1; i < 32; i++) m2 = fmaxf(m2, s_red[i]);
        s_v = m2;
    }
    __syncthreads();
    float mx = s_v;
    float e0 = __expf(s_x[tid]        - mx);
    float e1 = __expf(s_x[tid + 1024] - mx);
    float e2 = __expf(s_x[tid + 2048] - mx);
    float lsum = e0 + e1 + e2;
    #pragma unroll
    for (int o = 16; o > 0; o >>= 1)
        lsum += __shfl_xor_sync(0xffffffffu, lsum, o);
    __syncthreads();
    if ((tid & 31) == 0) s_red[tid >> 5] = lsum;
    __syncthreads();
    if (tid == 0) {
        float s = 0.f;
        #pragma unroll
        for (int i = 0; i < 32; i++) s += s_red[i];
        s_v = 1.f / s;
    }
    __syncthreads();
    float inv = s_v;
    float* att = g_att + (g * 4 + h) * 3072;
    att[tid]        = e0 * inv;
    att[tid + 1024] = e1 * inv;
    att[tid + 2048] = e2 * inv;
}

// ======= kernel D: message-passing scatter (16 lanes/edge, float4 atomics) =======
// blocks 0-35 also reset the tournament table (nothing reads g_tab this launch)
__global__ void __launch_bounds__(256) kD(
    const int* src, const int* dst, const int* lgs, const int* lgd, float* out)
{
    int tid = threadIdx.x;
    int bx = blockIdx.x;

    if (bx < 36) {
        int e = bx * 256 + tid;
        if (e < EE) g_tab[src[e] * 3072 + dst[e]] = 0;
        else {
            int l = e - EE;
            g_tab[TABH + lgs[l] * 3072 + lgd[l]] = 0;
        }
    }

    int u = tid >> 4;            // 16 edges per block
    int q = (tid & 15) * 4;      // float4 lane within feature dim
    if (bx < 192) {                                    // node messages (edge att, g=1)
        int e = bx * 16 + u;
        if (!g_winN[e]) return;
        int s = src[e], d = dst[e];
        float4 acc = make_float4(0.f, 0.f, 0.f, 0.f);
        #pragma unroll
        for (int h = 0; h < 4; h++) {
            float a = __ldg(&g_att[(4 + h) * 3072 + e]);
            float4 v = *(const float4*)&g_NV[((size_t)(h * 3072 + d)) * 64 + q];
            acc.x += a * v.x; acc.y += a * v.y; acc.z += a * v.z; acc.w += a * v.w;
        }
        acc.x *= 0.25f; acc.y *= 0.25f; acc.z *= 0.25f; acc.w *= 0.25f;
        atomicAdd((float4*)&out[s * 64 + q], acc);     // mean over heads
    } else {                                           // line-graph messages (node att, g=0)
        int l = (bx - 192) * 16 + u;
        if (!g_winL[l]) return;
        int e1 = lgs[l], e2 = lgd[l];
        int c = dst[e1];
        float4 acc = make_float4(0.f, 0.f, 0.f, 0.f);
        #pragma unroll
        for (int h = 0; h < 4; h++) {
            float a = __ldg(&g_att[h * 3072 + c]);
            float4 v = *(const float4*)&g_EV[((size_t)(h * 3072 + e2)) * 64 + q];
            acc.x += a * v.x; acc.y += a * v.y; acc.z += a * v.z; acc.w += a * v.w;
        }
        acc.x *= 0.25f; acc.y *= 0.25f; acc.z *= 0.25f; acc.w *= 0.25f;
        atomicAdd((float4*)&out[NN * 64 + e1 * 64 + q], acc);
    }
}

extern "C" void kernel_launch(void* const* d_in, const int* in_sizes, int n_in,
                              void* d_out, int out_size)
{
    const float* nin = (const float*)d_in[0];
    const float* ein = (const float*)d_in[1];
    const int* src = (const int*)d_in[2];
    const int* dst = (const int*)d_in[3];
    const int* lgs = (const int*)d_in[4];
    const int* lgd = (const int*)d_in[5];
    const float* nqW = (const float*)d_in[6];  const float* nqb = (const float*)d_in[7];
    const float* nkW = (const float*)d_in[8];  const float* nkb = (const float*)d_in[9];
    const float* nvW = (const float*)d_in[10]; const float* nvb = (const float*)d_in[11];
    const float* eqW = (const float*)d_in[12]; const float* eqb = (const float*)d_in[13];
    const float* ekW = (const float*)d_in[14]; const float* ekb = (const float*)d_in[15];
    const float* evW = (const float*)d_in[16]; const float* evb = (const float*)d_in[17];
    float* out = (float*)d_out;

    kA<<<908, 256>>>(nin, ein, nkW, nkb, ekW, ekb, nvW, nvb, evW, evb,
                     nqW, eqW, src, dst, lgs, lgd, out);
    kBC<<<17, 1024>>>(nin, ein, nqb, eqb, src, dst, lgs, lgd);
    kD<<<576, 256>>>(src, dst, lgs, lgd, out);
}

// round 6
// speedup vs baseline: 1.0783x; 1.0783x over previous
#include <cuda_runtime.h>

#define NN   3072
#define EE   3072
#define ELG  6144
#define FF   64
#define HH   4
#define RPH  768        // input rows per head after .view scramble
#define TABH 9437184    // 3072*3072, lg keys offset by this

// -------- scratch (__device__ globals; no allocations allowed) --------
__device__ float g_NV[NN * 256];
__device__ float g_EV[EE * 256];
__device__ float g_srkp[2 * 48 * 4 * 64];   // partial srk sums [g][chunk][h][f]
__device__ float g_WT[2 * 256 * 64];        // transposed Wq (node, edge)
__device__ float g_att[2 * 4 * 3072];       // g=0: node att, g=1: edge att
__device__ unsigned char g_winN[EE];
__device__ unsigned char g_winL[ELG];
__device__ int g_tab[2 * TABH];             // dedup tournament table (zero invariant)

// packed f32x2 helpers (FFMA2 path — ptxas never emits this from plain C++)
__device__ __forceinline__ unsigned long long pk2(float w) {
    unsigned long long r;
    asm("mov.b64 %0, {%1, %1};" : "=l"(r) : "f"(w));
    return r;
}
__device__ __forceinline__ void ffma2(unsigned long long& d,
                                      unsigned long long a, unsigned long long b) {
    asm("fma.rn.f32x2 %0, %1, %2, %0;" : "+l"(d) : "l"(a), "l"(b));
}
__device__ __forceinline__ void unpk2(unsigned long long v, float& lo, float& hi) {
    asm("mov.b64 {%0, %1}, %2;" : "=f"(lo), "=f"(hi) : "l"(v));
}

// ======================= kernel A: all input-only work =======================
// roles by blockIdx.x:
//   [0,96)      srk partials (fused K projection, never materialized)
//   [96,288)    V gemms: 128x64 tiles, NV (96 blocks), EV (96 blocks)
//   [288,324)   dedup atomicMax tournament (9216 edges)
//   [324,708)   zero output
//   [708,716)   transpose Wq (node 4 tiles, edge 4 tiles)
__global__ void __launch_bounds__(256) kA(
    const float* nin, const float* ein,
    const float* nkW, const float* nkb, const float* ekW, const float* ekb,
    const float* nvW, const float* nvb, const float* evW, const float* evb,
    const float* nqW, const float* eqW,
    const int* src, const int* dst, const int* lgs, const int* lgd,
    float* out)
{
    __shared__ __align__(16) float sm[8448];   // unioned per role (33.8KB)
    int b = blockIdx.x, tid = threadIdx.x;

    if (b < 96) {
        // ---- srk role: chunk of 64 nodes (16 KM rows per head) ----
        int g = b / 48, chunk = b % 48;
        const float* in = g ? ein : nin;
        const float* W  = g ? ekW : nkW;
        const float* bk = g ? ekb : nkb;
        float* s_in4 = sm;           // 4 heads * 16 rows * stride 68 = 4352
        float* s_wT  = sm + 4352;    // 4 * 68
        float* s_km  = sm + 4624;    // 4 * 64

        #pragma unroll
        for (int h2 = 0; h2 < 4; h2++) {
            #pragma unroll
            for (int i = 0; i < 4; i++) {
                int idx = i * 256 + tid;
                int rr = idx >> 6, kk = idx & 63;
                s_in4[h2 * 1088 + rr * 68 + kk] =
                    in[(h2 * RPH + chunk * 16 + rr) * 64 + kk];
            }
        }
        {   // transpose tiny K weights: s_wT[c][k] = W[k*4+c]
            int k = tid >> 2, c = tid & 3;
            s_wT[c * 68 + k] = W[tid];
        }
        __syncthreads();
        // phase 1: k[h, n] = KM[h*768 + n/4, n%4]
        int h = tid >> 6, idx = tid & 63;
        int rl = idx >> 2, c = idx & 3;
        float acc = bk[c];
        const float4* arow = (const float4*)&s_in4[h * 1088 + rl * 68];
        const float4* wrow = (const float4*)&s_wT[c * 68];
        #pragma unroll
        for (int k4 = 0; k4 < 16; k4++) {
            float4 a = arow[k4], w = wrow[k4];
            acc += a.x * w.x + a.y * w.y + a.z * w.z + a.w * w.w;
        }
        s_km[h * 64 + rl * 4 + c] = acc;   // index == h*64 + local n
        __syncthreads();
        // phase 2: srk partial: srk[h,f] += in[n,f] * k[h,n] over 64 n
        int f = tid & 63;
        float sacc = 0.f;
        int n0 = chunk * 64;
        #pragma unroll 8
        for (int nl = 0; nl < 64; nl++)
            sacc += in[(n0 + nl) * 64 + f] * s_km[h * 64 + nl];
        g_srkp[((g * 48 + chunk) * 4 + h) * 64 + f] = sacc;

    } else if (b < 288) {
        // ---- V gemm role: [3072x64] @ [64x256] + bias, 128x64 tile ----
        // 8 rows x 4 cols per thread, W streamed from gmem (L2-hot),
        // A transposed k-major in smem (stride 132, f32x2 row-pairs).
        int i2 = b - 96;
        int mat = i2 / 96;
        int rem = i2 % 96;                      // 24 r-tiles x 4 c-tiles
        int r0 = (rem >> 2) * 128, c0 = (rem & 3) * 64;
        const float* in = mat ? ein : nin;
        const float* W  = mat ? evW : nvW;
        const float* bb = mat ? evb : nvb;
        float* outv     = mat ? g_EV : g_NV;
        float* As = sm;                         // 64 k * stride 132 = 8448

        #pragma unroll
        for (int i = 0; i < 32; i++) {
            int idx = i * 256 + tid;
            int r = idx >> 6, k = idx & 63;
            As[k * 132 + r] = in[r0 * 64 + idx];
        }
        __syncthreads();

        int tx = tid & 15, ty = tid >> 4;
        int rl = ty * 8, cl = tx * 4;
        unsigned long long acc2[4][4];          // 4 row-pairs x 4 cols
        #pragma unroll
        for (int p = 0; p < 4; p++)
            #pragma unroll
            for (int j = 0; j < 4; j++) acc2[p][j] = 0ull;

        #pragma unroll 16
        for (int k = 0; k < 64; k++) {
            ulonglong2 a01 = *(const ulonglong2*)&As[k * 132 + rl];
            ulonglong2 a23 = *(const ulonglong2*)&As[k * 132 + rl + 4];
            float4 w = __ldg((const float4*)&W[k * 256 + c0 + cl]);
            unsigned long long wx = pk2(w.x), wy = pk2(w.y),
                               wz = pk2(w.z), ww = pk2(w.w);
            ffma2(acc2[0][0], a01.x, wx); ffma2(acc2[1][0], a01.y, wx);
            ffma2(acc2[2][0], a23.x, wx); ffma2(acc2[3][0], a23.y, wx);
            ffma2(acc2[0][1], a01.x, wy); ffma2(acc2[1][1], a01.y, wy);
            ffma2(acc2[2][1], a23.x, wy); ffma2(acc2[3][1], a23.y, wy);
            ffma2(acc2[0][2], a01.x, wz); ffma2(acc2[1][2], a01.y, wz);
            ffma2(acc2[2][2], a23.x, wz); ffma2(acc2[3][2], a23.y, wz);
            ffma2(acc2[0][3], a01.x, ww); ffma2(acc2[1][3], a01.y, ww);
            ffma2(acc2[2][3], a23.x, ww); ffma2(acc2[3][3], a23.y, ww);
        }
        float4 bias = __ldg((const float4*)&bb[c0 + cl]);
        #pragma unroll
        for (int p = 0; p < 4; p++) {
            float lo[4], hi[4];
            #pragma unroll
            for (int j = 0; j < 4; j++) unpk2(acc2[p][j], lo[j], hi[j]);
            *(float4*)&outv[(r0 + rl + 2 * p)     * 256 + c0 + cl] =
                make_float4(lo[0] + bias.x, lo[1] + bias.y,
                            lo[2] + bias.z, lo[3] + bias.w);
            *(float4*)&outv[(r0 + rl + 2 * p + 1) * 256 + c0 + cl] =
                make_float4(hi[0] + bias.x, hi[1] + bias.y,
                            hi[2] + bias.z, hi[3] + bias.w);
        }

    } else if (b < 324) {
        // ---- dedup tournament: atomicMax(tab[key], e+1) ----
        int e = (b - 288) * 256 + tid;
        if (e < EE) {
            atomicMax(&g_tab[src[e] * 3072 + dst[e]], e + 1);
        } else {
            int l = e - EE;
            atomicMax(&g_tab[TABH + lgs[l] * 3072 + lgd[l]], l + 1);
        }

    } else if (b < 708) {
        // ---- zero output ----
        int idx = (b - 324) * 256 + tid;
        ((float4*)out)[idx] = make_float4(0.f, 0.f, 0.f, 0.f);

    } else {
        // ---- transpose Wq: [64k][256c] -> WT[256c][64k] ----
        int t = b - 708;
        int mat = t >> 2, tile = t & 3;
        const float* W = mat ? eqW : nqW;
        float* s = sm;   // 64*65
        #pragma unroll
        for (int i = 0; i < 16; i++) {
            int idx = i * 256 + tid;
            int k = idx >> 6, c = idx & 63;
            s[k * 65 + c] = W[k * 256 + tile * 64 + c];
        }
        __syncthreads();
        #pragma unroll
        for (int i = 0; i < 16; i++) {
            int idx = i * 256 + tid;
            int c = idx >> 6, k = idx & 63;
            g_WT[mat * 16384 + (tile * 64 + c) * 64 + k] = s[k * 65 + c];
        }
    }
}

// ===== kernel BC: fused srk-reduce + c/d + logits + softmax (blocks 0-7) =====
// ===== blocks 8-16: read dedup winners from tournament table            =====
__global__ void __launch_bounds__(1024) kBC(
    const float* nin, const float* ein, const float* nqb, const float* eqb,
    const int* src, const int* dst, const int* lgs, const int* lgd)
{
    int tid = threadIdx.x;
    if (blockIdx.x >= 8) {
        int idx = (blockIdx.x - 8) * 1024 + tid;
        if (idx < EE) {
            g_winN[idx] = (g_tab[src[idx] * 3072 + dst[idx]] == idx + 1);
        } else if (idx < EE + ELG) {
            int l = idx - EE;
            g_winL[l] = (g_tab[TABH + lgs[l] * 3072 + lgd[l]] == l + 1);
        }
        return;
    }

    __shared__ __align__(16) float s_rows[128 * 68];  // staging (also phase-1 scratch)
    __shared__ float s_srk[64];
    __shared__ __align__(16) float s_c[4 * 68];
    __shared__ float s_d[4];
    __shared__ float s_red[32];
    __shared__ float s_v;

    int g = blockIdx.x >> 2, h = blockIdx.x & 3;
    const float* in = g ? ein : nin;

    // ---- phase 1: reduce srk partials (48 chunks), scratch = s_rows ----
    float* s_part = s_rows;
    {
        int f = tid & 63, p = tid >> 6;    // 16 groups x 3 chunks
        float a = 0.f;
        #pragma unroll
        for (int q = 0; q < 3; q++)
            a += g_srkp[((g * 48 + p * 3 + q) * 4 + h) * 64 + f];
        s_part[tid] = a;
    }
    __syncthreads();
    if (tid < 64) {
        float a = 0.f;
        #pragma unroll
        for (int p = 0; p < 16; p++) a += s_part[p * 64 + tid];
        s_srk[tid] = a;
    }
    __syncthreads();

    // ---- phase 2: c[j][k] = sum_f Wq[k,64j+f]*srk[f];  d[j] = bq[j]::srk ----
    if (tid < 256) {
        int j = tid & 3, k = tid >> 2;
        const float* wt = g_WT + g * 16384 + j * 4096;   // WT[(j*64+f)*64 + k]
        float a = 0.f;
        #pragma unroll
        for (int f = 0; f < 64; f++)
            a += wt[f * 64 + k] * s_srk[f];
        s_c[j * 68 + k] = a;
    } else if (tid < 260) {
        int j = tid - 256;
        const float* bq = g ? eqb : nqb;
        float dd = 0.f;
        #pragma unroll
        for (int f = 0; f < 64; f++) dd += bq[j * 64 + f] * s_srk[f];
        s_d[j] = dd;
    }
    __syncthreads();

    // ---- phase 3: logits in registers, staged through smem 128 rows/chunk ----
    float x6[6];
    float lmax = -1e30f;
    int ml = tid >> 2, jj = tid & 3;      // (row-in-chunk, j) for tid < 512
    for (int chunk = 0; chunk < 6; chunk++) {
        const float4* src4 =
            (const float4*)(in + (size_t)(h * RPH + chunk * 128) * 64);
        #pragma unroll
        for (int i = 0; i < 2; i++) {
            int idx = i * 1024 + tid;      // 2048 float4 = 128 rows
            int r = idx >> 4, k4 = idx & 15;
            *(float4*)&s_rows[r * 68 + k4 * 4] = src4[idx];
        }
        __syncthreads();
        if (tid < 512) {
            const float4* row = (const float4*)&s_rows[ml * 68];
            const float4* cj  = (const float4*)&s_c[jj * 68];
            float a0 = 0.f, a1 = 0.f, a2 = 0.f, a3 = 0.f;
            #pragma unroll
            for (int k = 0; k < 16; k += 4) {
                float4 r0 = row[k + 0], c0 = cj[k + 0];
                float4 r1 = row[k + 1], c1 = cj[k + 1];
                float4 r2 = row[k + 2], c2 = cj[k + 2];
                float4 r3 = row[k + 3], c3 = cj[k + 3];
                a0 += r0.x * c0.x + r0.y * c0.y + r0.z * c0.z + r0.w * c0.w;
                a1 += r1.x * c1.x + r1.y * c1.y + r1.z * c1.z + r1.w * c1.w;
                a2 += r2.x * c2.x + r2.y * c2.y + r2.z * c2.z + r2.w * c2.w;
                a3 += r3.x * c3.x + r3.y * c3.y + r3.z * c3.z + r3.w * c3.w;
            }
            float x = (s_d[jj] + ((a0 + a1) + (a2 + a3))) * 0.125f;
            x6[chunk] = x;
            lmax = fmaxf(lmax, x);
        }
        __syncthreads();
    }

    // ---- phase 4: softmax over 3072 (values live in x6 of threads < 512) ----
    #pragma unroll
    for (int o = 16; o > 0; o >>= 1)
        lmax = fmaxf(lmax, __shfl_xor_sync(0xffffffffu, lmax, o));
    if ((tid & 31) == 0) s_red[tid >> 5] = lmax;
    __syncthreads();
    if (tid == 0) {
        float m2 = s_red[0];
        #pragma unroll
        for (int i = 1; i < 32; i++) m2 = fmaxf(m2, s_red[i]);
        s_v = m2;
    }
    __syncthreads();
    float mx = s_v;
    float e6[6];
    float lsum = 0.f;
    if (tid < 512) {
        #pragma unroll
        for (int c = 0; c < 6; c++) {
            e6[c] = __expf(x6[c] - mx);
            lsum += e6[c];
        }
    }
    #pragma unroll
    for (int o = 16; o > 0; o >>= 1)
        lsum += __shfl_xor_sync(0xffffffffu, lsum, o);
    __syncthreads();
    if ((tid & 31) == 0) s_red[tid >> 5] = lsum;
    __syncthreads();
    if (tid == 0) {
        float s = 0.f;
        #pragma unroll
        for (int i = 0; i < 32; i++) s += s_red[i];
        s_v = 1.f / s;
    }
    __syncthreads();
    float inv = s_v;
    if (tid < 512) {
        float* att = g_att + (g * 4 + h) * 3072;
        #pragma unroll
        for (int c = 0; c < 6; c++)
            att[(c * 128 + ml) * 4 + jj] = e6[c] * inv;
    }
}

// ======= kernel D: message-passing scatter (16 lanes/edge, float4 atomics) =======
// blocks 0-35 also reset the tournament table (nothing reads g_tab this launch)
__global__ void __launch_bounds__(256) kD(
    const int* src, const int* dst, const int* lgs, const int* lgd, float* out)
{
    int tid = threadIdx.x;
    int bx = blockIdx.x;

    if (bx < 36) {
        int e = bx * 256 + tid;
        if (e < EE) g_tab[src[e] * 3072 + dst[e]] = 0;
        else {
            int l = e - EE;
            g_tab[TABH + lgs[l] * 3072 + lgd[l]] = 0;
        }
    }

    int u = tid >> 4;            // 16 edges per block
    int q = (tid & 15) * 4;      // float4 lane within feature dim
    if (bx < 192) {                                    // node messages (edge att, g=1)
        int e = bx * 16 + u;
        if (!g_winN[e]) return;
        int s = src[e], d = dst[e];
        float4 acc = make_float4(0.f, 0.f, 0.f, 0.f);
        #pragma unroll
        for (int h = 0; h < 4; h++) {
            float a = __ldg(&g_att[(4 + h) * 3072 + e]);
            float4 v = *(const float4*)&g_NV[((size_t)(h * 3072 + d)) * 64 + q];
            acc.x += a * v.x; acc.y += a * v.y; acc.z += a * v.z; acc.w += a * v.w;
        }
        acc.x *= 0.25f; acc.y *= 0.25f; acc.z *= 0.25f; acc.w *= 0.25f;
        atomicAdd((float4*)&out[s * 64 + q], acc);     // mean over heads
    } else {                                           // line-graph messages (node att, g=0)
        int l = (bx - 192) * 16 + u;
        if (!g_winL[l]) return;
        int e1 = lgs[l], e2 = lgd[l];
        int c = dst[e1];
        float4 acc = make_float4(0.f, 0.f, 0.f, 0.f);
        #pragma unroll
        for (int h = 0; h < 4; h++) {
            float a = __ldg(&g_att[h * 3072 + c]);
            float4 v = *(const float4*)&g_EV[((size_t)(h * 3072 + e2)) * 64 + q];
            acc.x += a * v.x; acc.y += a * v.y; acc.z += a * v.z; acc.w += a * v.w;
        }
        acc.x *= 0.25f; acc.y *= 0.25f; acc.z *= 0.25f; acc.w *= 0.25f;
        atomicAdd((float4*)&out[NN * 64 + e1 * 64 + q], acc);
    }
}

extern "C" void kernel_launch(void* const* d_in, const int* in_sizes, int n_in,
                              void* d_out, int out_size)
{
    const float* nin = (const float*)d_in[0];
    const float* ein = (const float*)d_in[1];
    const int* src = (const int*)d_in[2];
    const int* dst = (const int*)d_in[3];
    const int* lgs = (const int*)d_in[4];
    const int* lgd = (const int*)d_in[5];
    const float* nqW = (const float*)d_in[6];  const float* nqb = (const float*)d_in[7];
    const float* nkW = (const float*)d_in[8];  const float* nkb = (const float*)d_in[9];
    const float* nvW = (const float*)d_in[10]; const float* nvb = (const float*)d_in[11];
    const float* eqW = (const float*)d_in[12]; const float* eqb = (const float*)d_in[13];
    const float* ekW = (const float*)d_in[14]; const float* ekb = (const float*)d_in[15];
    const float* evW = (const float*)d_in[16]; const float* evb = (const float*)d_in[17];
    float* out = (float*)d_out;

    kA<<<716, 256>>>(nin, ein, nkW, nkb, ekW, ekb, nvW, nvb, evW, evb,
                     nqW, eqW, src, dst, lgs, lgd, out);
    kBC<<<17, 1024>>>(nin, ein, nqb, eqb, src, dst, lgs, lgd);
    kD<<<576, 256>>>(src, dst, lgs, lgd, out);
}

// round 7
// speedup vs baseline: 1.0866x; 1.0077x over previous
#include <cuda_runtime.h>

#define NN   3072
#define EE   3072
#define ELG  6144
#define FF   64
#define HH   4
#define RPH  768        // input rows per head after .view scramble
#define TABH 9437184    // 3072*3072, lg keys offset by this

// -------- scratch (__device__ globals; no allocations allowed) --------
__device__ float g_NV[NN * 256];
__device__ float g_EV[EE * 256];
__device__ float g_srkp[2 * 48 * 4 * 64];   // partial srk sums [g][chunk][h][f]
__device__ float g_WT[2 * 256 * 64];        // transposed Wq (node, edge)
__device__ float g_att[2 * 4 * 3072];       // g=0: node att, g=1: edge att
__device__ unsigned char g_winN[EE];
__device__ unsigned char g_winL[ELG];
__device__ int g_tab[2 * TABH];             // dedup tournament table (zero invariant)

// packed f32x2 helpers (FFMA2 path — ptxas never emits this from plain C++)
__device__ __forceinline__ unsigned long long pk2(float w) {
    unsigned long long r;
    asm("mov.b64 %0, {%1, %1};" : "=l"(r) : "f"(w));
    return r;
}
__device__ __forceinline__ void ffma2(unsigned long long& d,
                                      unsigned long long a, unsigned long long b) {
    asm("fma.rn.f32x2 %0, %1, %2, %0;" : "+l"(d) : "l"(a), "l"(b));
}
__device__ __forceinline__ void unpk2(unsigned long long v, float& lo, float& hi) {
    asm("mov.b64 {%0, %1}, %2;" : "=f"(lo), "=f"(hi) : "l"(v));
}

// ======================= kernel A: all input-only work =======================
// roles by blockIdx.x:
//   [0,96)      srk partials (fused K projection, never materialized)
//   [96,480)    V gemms: 64x64 tiles, NV (192 blocks), EV (192 blocks)
//   [480,516)   dedup atomicMax tournament (9216 edges)
//   [516,524)   transpose Wq (node 4 tiles, edge 4 tiles)
__global__ void __launch_bounds__(256) kA(
    const float* nin, const float* ein,
    const float* nkW, const float* nkb, const float* ekW, const float* ekb,
    const float* nvW, const float* nvb, const float* evW, const float* evb,
    const float* nqW, const float* eqW,
    const int* src, const int* dst, const int* lgs, const int* lgd)
{
    __shared__ __align__(16) float sm[8512];   // unioned per role (~34KB)
    int b = blockIdx.x, tid = threadIdx.x;

    if (b < 96) {
        // ---- srk role: chunk of 64 nodes (16 KM rows per head) ----
        int g = b / 48, chunk = b % 48;
        const float* in = g ? ein : nin;
        const float* W  = g ? ekW : nkW;
        const float* bk = g ? ekb : nkb;
        float* s_in4 = sm;           // 4 heads * 16 rows * stride 68 = 4352
        float* s_wT  = sm + 4352;    // 4 * 68
        float* s_km  = sm + 4624;    // 4 * 64

        #pragma unroll
        for (int h2 = 0; h2 < 4; h2++) {
            #pragma unroll
            for (int i = 0; i < 4; i++) {
                int idx = i * 256 + tid;
                int rr = idx >> 6, kk = idx & 63;
                s_in4[h2 * 1088 + rr * 68 + kk] =
                    in[(h2 * RPH + chunk * 16 + rr) * 64 + kk];
            }
        }
        {   // transpose tiny K weights: s_wT[c][k] = W[k*4+c]
            int k = tid >> 2, c = tid & 3;
            s_wT[c * 68 + k] = W[tid];
        }
        __syncthreads();
        // phase 1: k[h, n] = KM[h*768 + n/4, n%4]
        int h = tid >> 6, idx = tid & 63;
        int rl = idx >> 2, c = idx & 3;
        float acc = bk[c];
        const float4* arow = (const float4*)&s_in4[h * 1088 + rl * 68];
        const float4* wrow = (const float4*)&s_wT[c * 68];
        #pragma unroll
        for (int k4 = 0; k4 < 16; k4++) {
            float4 a = arow[k4], w = wrow[k4];
            acc += a.x * w.x + a.y * w.y + a.z * w.z + a.w * w.w;
        }
        s_km[h * 64 + rl * 4 + c] = acc;   // index == h*64 + local n
        __syncthreads();
        // phase 2: srk partial: srk[h,f] += in[n,f] * k[h,n] over 64 n
        int f = tid & 63;
        float sacc = 0.f;
        int n0 = chunk * 64;
        #pragma unroll 8
        for (int nl = 0; nl < 64; nl++)
            sacc += in[(n0 + nl) * 64 + f] * s_km[h * 64 + nl];
        g_srkp[((g * 48 + chunk) * 4 + h) * 64 + f] = sacc;

    } else if (b < 480) {
        // ---- V gemm role: [3072x64] @ [64x256] + bias, f32x2-packed ----
        int i2 = b - 96;
        int mat = i2 / 192;
        int rem = i2 % 192;
        int r0 = (rem >> 2) * 64, c0 = (rem & 3) * 64;
        const float* in = mat ? ein : nin;
        const float* W  = mat ? evW : nvW;
        const float* bb = mat ? evb : nvb;
        float* outv     = mat ? g_EV : g_NV;
        float* As = sm;                  // 64 k * stride 68 = 4352
        float* Ws = sm + 4352;           // 64*64
        float* Bs = sm + 8448;           // 64

        #pragma unroll
        for (int i = 0; i < 16; i++) {
            int idx = i * 256 + tid;
            int r = idx >> 6, k = idx & 63;
            As[k * 68 + r] = in[r0 * 64 + idx];
        }
        #pragma unroll
        for (int i = 0; i < 16; i++) {
            int idx = i * 256 + tid;
            int k = idx >> 6, cc = idx & 63;
            Ws[k * 64 + cc] = W[k * 256 + c0 + cc];
        }
        if (tid < 64) Bs[tid] = bb[c0 + tid];
        __syncthreads();

        int tx = tid & 15, ty = tid >> 4;
        int rl = ty * 4, cl = tx * 4;
        unsigned long long acc2[2][4];   // row-pairs (rl+2p, rl+2p+1) x 4 cols
        #pragma unroll
        for (int j = 0; j < 4; j++) {
            unsigned long long p = pk2(Bs[cl + j]);
            acc2[0][j] = p; acc2[1][j] = p;
        }

        #pragma unroll 16
        for (int k = 0; k < 64; k++) {
            ulonglong2 a = *(const ulonglong2*)&As[k * 68 + rl];
            float4 w = *(const float4*)&Ws[k * 64 + cl];
            unsigned long long wx = pk2(w.x), wy = pk2(w.y),
                               wz = pk2(w.z), ww = pk2(w.w);
            ffma2(acc2[0][0], a.x, wx); ffma2(acc2[1][0], a.y, wx);
            ffma2(acc2[0][1], a.x, wy); ffma2(acc2[1][1], a.y, wy);
            ffma2(acc2[0][2], a.x, wz); ffma2(acc2[1][2], a.y, wz);
            ffma2(acc2[0][3], a.x, ww); ffma2(acc2[1][3], a.y, ww);
        }
        #pragma unroll
        for (int p = 0; p < 2; p++) {
            float lo[4], hi[4];
            #pragma unroll
            for (int j = 0; j < 4; j++) unpk2(acc2[p][j], lo[j], hi[j]);
            *(float4*)&outv[(r0 + rl + 2 * p)     * 256 + c0 + cl] =
                make_float4(lo[0], lo[1], lo[2], lo[3]);
            *(float4*)&outv[(r0 + rl + 2 * p + 1) * 256 + c0 + cl] =
                make_float4(hi[0], hi[1], hi[2], hi[3]);
        }

    } else if (b < 516) {
        // ---- dedup tournament: atomicMax(tab[key], e+1) ----
        int e = (b - 480) * 256 + tid;
        if (e < EE) {
            atomicMax(&g_tab[src[e] * 3072 + dst[e]], e + 1);
        } else {
            int l = e - EE;
            atomicMax(&g_tab[TABH + lgs[l] * 3072 + lgd[l]], l + 1);
        }

    } else {
        // ---- transpose Wq: [64k][256c] -> WT[256c][64k] ----
        int t = b - 516;
        int mat = t >> 2, tile = t & 3;
        const float* W = mat ? eqW : nqW;
        float* s = sm;   // 64*65
        #pragma unroll
        for (int i = 0; i < 16; i++) {
            int idx = i * 256 + tid;
            int k = idx >> 6, c = idx & 63;
            s[k * 65 + c] = W[k * 256 + tile * 64 + c];
        }
        __syncthreads();
        #pragma unroll
        for (int i = 0; i < 16; i++) {
            int idx = i * 256 + tid;
            int c = idx >> 6, k = idx & 63;
            g_WT[mat * 16384 + (tile * 64 + c) * 64 + k] = s[k * 65 + c];
        }
    }
}

// ===== kernel BC: fused srk-reduce + c/d + logits + softmax (blocks 0-7) =====
// ===== blocks 8-16: read dedup winners from tournament table            =====
__global__ void __launch_bounds__(1024) kBC(
    const float* nin, const float* ein, const float* nqb, const float* eqb,
    const int* src, const int* dst, const int* lgs, const int* lgd)
{
    int tid = threadIdx.x;
    if (blockIdx.x >= 8) {
        int idx = (blockIdx.x - 8) * 1024 + tid;
        if (idx < EE) {
            g_winN[idx] = (g_tab[src[idx] * 3072 + dst[idx]] == idx + 1);
        } else if (idx < EE + ELG) {
            int l = idx - EE;
            g_winL[l] = (g_tab[TABH + lgs[l] * 3072 + lgd[l]] == l + 1);
        }
        return;
    }

    __shared__ __align__(16) float s_rows[128 * 68];  // staging (also phase-1 scratch)
    __shared__ float s_srk[64];
    __shared__ __align__(16) float s_c[4 * 68];
    __shared__ float s_d[4];
    __shared__ float s_red[32];
    __shared__ float s_v;

    int g = blockIdx.x >> 2, h = blockIdx.x & 3;
    const float* in = g ? ein : nin;

    // ---- phase 1: reduce srk partials (48 chunks), scratch = s_rows ----
    float* s_part = s_rows;
    {
        int f = tid & 63, p = tid >> 6;    // 16 groups x 3 chunks
        float a = 0.f;
        #pragma unroll
        for (int q = 0; q < 3; q++)
            a += g_srkp[((g * 48 + p * 3 + q) * 4 + h) * 64 + f];
        s_part[tid] = a;
    }
    __syncthreads();
    if (tid < 64) {
        float a = 0.f;
        #pragma unroll
        for (int p = 0; p < 16; p++) a += s_part[p * 64 + tid];
        s_srk[tid] = a;
    }
    __syncthreads();

    // ---- phase 2: c[j][k] = sum_f Wq[k,64j+f]*srk[f];  d[j] = bq[j]::srk ----
    if (tid < 256) {
        int j = tid & 3, k = tid >> 2;
        const float* wt = g_WT + g * 16384 + j * 4096;   // WT[(j*64+f)*64 + k]
        float a = 0.f;
        #pragma unroll
        for (int f = 0; f < 64; f++)
            a += wt[f * 64 + k] * s_srk[f];
        s_c[j * 68 + k] = a;
    } else if (tid < 260) {
        int j = tid - 256;
        const float* bq = g ? eqb : nqb;
        float dd = 0.f;
        #pragma unroll
        for (int f = 0; f < 64; f++) dd += bq[j * 64 + f] * s_srk[f];
        s_d[j] = dd;
    }
    __syncthreads();

    // ---- phase 3: logits in registers, staged through smem 128 rows/chunk ----
    float x6[6];
    float lmax = -1e30f;
    int ml = tid >> 2, jj = tid & 3;      // (row-in-chunk, j) for tid < 512
    for (int chunk = 0; chunk < 6; chunk++) {
        const float4* src4 =
            (const float4*)(in + (size_t)(h * RPH + chunk * 128) * 64);
        #pragma unroll
        for (int i = 0; i < 2; i++) {
            int idx = i * 1024 + tid;      // 2048 float4 = 128 rows
            int r = idx >> 4, k4 = idx & 15;
            *(float4*)&s_rows[r * 68 + k4 * 4] = src4[idx];
        }
        __syncthreads();
        if (tid < 512) {
            const float4* row = (const float4*)&s_rows[ml * 68];
            const float4* cj  = (const float4*)&s_c[jj * 68];
            float a0 = 0.f, a1 = 0.f, a2 = 0.f, a3 = 0.f;
            #pragma unroll
            for (int k = 0; k < 16; k += 4) {
                float4 r0 = row[k + 0], c0 = cj[k + 0];
                float4 r1 = row[k + 1], c1 = cj[k + 1];
                float4 r2 = row[k + 2], c2 = cj[k + 2];
                float4 r3 = row[k + 3], c3 = cj[k + 3];
                a0 += r0.x * c0.x + r0.y * c0.y + r0.z * c0.z + r0.w * c0.w;
                a1 += r1.x * c1.x + r1.y * c1.y + r1.z * c1.z + r1.w * c1.w;
                a2 += r2.x * c2.x + r2.y * c2.y + r2.z * c2.z + r2.w * c2.w;
                a3 += r3.x * c3.x + r3.y * c3.y + r3.z * c3.z + r3.w * c3.w;
            }
            float x = (s_d[jj] + ((a0 + a1) + (a2 + a3))) * 0.125f;
            x6[chunk] = x;
            lmax = fmaxf(lmax, x);
        }
        __syncthreads();
    }

    // ---- phase 4: softmax over 3072 (values live in x6 of threads < 512) ----
    #pragma unroll
    for (int o = 16; o > 0; o >>= 1)
        lmax = fmaxf(lmax, __shfl_xor_sync(0xffffffffu, lmax, o));
    if ((tid & 31) == 0) s_red[tid >> 5] = lmax;
    __syncthreads();
    if (tid == 0) {
        float m2 = s_red[0];
        #pragma unroll
        for (int i = 1; i < 32; i++) m2 = fmaxf(m2, s_red[i]);
        s_v = m2;
    }
    __syncthreads();
    float mx = s_v;
    float e6[6];
    float lsum = 0.f;
    if (tid < 512) {
        #pragma unroll
        for (int c = 0; c < 6; c++) {
            e6[c] = __expf(x6[c] - mx);
            lsum += e6[c];
        }
    }
    #pragma unroll
    for (int o = 16; o > 0; o >>= 1)
        lsum += __shfl_xor_sync(0xffffffffu, lsum, o);
    __syncthreads();
    if ((tid & 31) == 0) s_red[tid >> 5] = lsum;
    __syncthreads();
    if (tid == 0) {
        float s = 0.f;
        #pragma unroll
        for (int i = 0; i < 32; i++) s += s_red[i];
        s_v = 1.f / s;
    }
    __syncthreads();
    float inv = s_v;
    if (tid < 512) {
        float* att = g_att + (g * 4 + h) * 3072;
        #pragma unroll
        for (int c = 0; c < 6; c++)
            att[(c * 128 + ml) * 4 + jj] = e6[c] * inv;
    }
}

// ======= kernel D: message-passing scatter (16 lanes/edge, float4 atomics) =======
// blocks 0-35 also reset the tournament table (nothing reads g_tab this launch)
__global__ void __launch_bounds__(256) kD(
    const int* src, const int* dst, const int* lgs, const int* lgd, float* out)
{
    int tid = threadIdx.x;
    int bx = blockIdx.x;

    if (bx < 36) {
        int e = bx * 256 + tid;
        if (e < EE) g_tab[src[e] * 3072 + dst[e]] = 0;
        else {
            int l = e - EE;
            g_tab[TABH + lgs[l] * 3072 + lgd[l]] = 0;
        }
    }

    int u = tid >> 4;            // 16 edges per block
    int q = (tid & 15) * 4;      // float4 lane within feature dim
    if (bx < 192) {                                    // node messages (edge att, g=1)
        int e = bx * 16 + u;
        if (!g_winN[e]) return;
        int s = src[e], d = dst[e];
        float4 acc = make_float4(0.f, 0.f, 0.f, 0.f);
        #pragma unroll
        for (int h = 0; h < 4; h++) {
            float a = __ldg(&g_att[(4 + h) * 3072 + e]);
            float4 v = *(const float4*)&g_NV[((size_t)(h * 3072 + d)) * 64 + q];
            acc.x += a * v.x; acc.y += a * v.y; acc.z += a * v.z; acc.w += a * v.w;
        }
        acc.x *= 0.25f; acc.y *= 0.25f; acc.z *= 0.25f; acc.w *= 0.25f;
        atomicAdd((float4*)&out[s * 64 + q], acc);     // mean over heads
    } else {                                           // line-graph messages (node att, g=0)
        int l = (bx - 192) * 16 + u;
        if (!g_winL[l]) return;
        int e1 = lgs[l], e2 = lgd[l];
        int c = dst[e1];
        float4 acc = make_float4(0.f, 0.f, 0.f, 0.f);
        #pragma unroll
        for (int h = 0; h < 4; h++) {
            float a = __ldg(&g_att[h * 3072 + c]);
            float4 v = *(const float4*)&g_EV[((size_t)(h * 3072 + e2)) * 64 + q];
            acc.x += a * v.x; acc.y += a * v.y; acc.z += a * v.z; acc.w += a * v.w;
        }
        acc.x *= 0.25f; acc.y *= 0.25f; acc.z *= 0.25f; acc.w *= 0.25f;
        atomicAdd((float4*)&out[NN * 64 + e1 * 64 + q], acc);
    }
}

extern "C" void kernel_launch(void* const* d_in, const int* in_sizes, int n_in,
                              void* d_out, int out_size)
{
    const float* nin = (const float*)d_in[0];
    const float* ein = (const float*)d_in[1];
    const int* src = (const int*)d_in[2];
    const int* dst = (const int*)d_in[3];
    const int* lgs = (const int*)d_in[4];
    const int* lgd = (const int*)d_in[5];
    const float* nqW = (const float*)d_in[6];  const float* nqb = (const float*)d_in[7];
    const float* nkW = (const float*)d_in[8];  const float* nkb = (const float*)d_in[9];
    const float* nvW = (const float*)d_in[10]; const float* nvb = (const float*)d_in[11];
    const float* eqW = (const float*)d_in[12]; const float* eqb = (const float*)d_in[13];
    const float* ekW = (const float*)d_in[14]; const float* ekb = (const float*)d_in[15];
    const float* evW = (const float*)d_in[16]; const float* evb = (const float*)d_in[17];
    float* out = (float*)d_out;

    cudaMemsetAsync(out, 0, (size_t)out_size * sizeof(float));

    kA<<<524, 256>>>(nin, ein, nkW, nkb, ekW, ekb, nvW, nvb, evW, evb,
                     nqW, eqW, src, dst, lgs, lgd);
    kBC<<<17, 1024>>>(nin, ein, nqb, eqb, src, dst, lgs, lgd);
    kD<<<576, 256>>>(src, dst, lgs, lgd, out);
}